// round 1
// baseline (speedup 1.0000x reference)
#include <cuda_runtime.h>
#include <math.h>

#define BATCH 64
#define NGT 40
#define CELLS_PER_B 33600   // 160*160 + 80*80 + 40*40
#define TOTC (BATCH*CELLS_PER_B)
#define CAP 1024
#define FEPS 1e-7f
#define NTHREADS 256

// ---- static device scratch (no allocations allowed) ----
__device__ float g_pcx[TOTC];
__device__ float g_pcy[TOTC];
__device__ float g_pw [TOTC];
__device__ float g_ph [TOTC];
__device__ float g_cls[TOTC];

__device__ float g_obj[TOTC];
__device__ float g_pm [TOTC];
__device__ float g_b0 [TOTC];
__device__ float g_b1 [TOTC];
__device__ float g_b2 [TOTC];
__device__ float g_b3 [TOTC];
__device__ float g_f0 [TOTC];
__device__ float g_f1 [TOTC];

__device__ double g_acc;

// IoU between a cell's predicted xyxy box and the GT xyxy box (normalized coords)
__device__ __forceinline__ float iou_cell(int gi, float tx1, float ty1, float tx2, float ty2, float ga) {
    float pcx = g_pcx[gi], pcy = g_pcy[gi], pw = g_pw[gi], ph = g_ph[gi];
    float px1 = pcx - pw * 0.5f, py1 = pcy - ph * 0.5f;
    float px2 = pcx + pw * 0.5f, py2 = pcy + ph * 0.5f;
    float iw = fminf(px2, tx2) - fmaxf(px1, tx1); iw = fmaxf(iw, 0.f);
    float ih = fminf(py2, ty2) - fmaxf(py1, ty1); ih = fmaxf(ih, 0.f);
    float inter = iw * ih;
    float aa = (px2 - px1) * (py2 - py1);
    return inter / (aa + ga - inter + FEPS);
}

// ---------------- precompute kernel ----------------
__global__ __launch_bounds__(NTHREADS) void k_pre(const float* __restrict__ p0,
                                                  const float* __restrict__ p1,
                                                  const float* __restrict__ p2) {
    int idx = blockIdx.x * blockDim.x + threadIdx.x;
    if (idx == 0) g_acc = 0.0;
    int nth = gridDim.x * blockDim.x;
    for (int i = idx; i < TOTC; i += nth) {
        int b = i / CELLS_PER_B;
        int r = i - b * CELLS_PER_B;
        const float* pr; int hw, W, cell; float s;
        if (r < 25600)      { pr = p0; hw = 25600; W = 160; cell = r;          s = 0.00625f; }
        else if (r < 32000) { pr = p1; hw = 6400;  W = 80;  cell = r - 25600;  s = 0.0125f; }
        else                { pr = p2; hw = 1600;  W = 40;  cell = r - 32000;  s = 0.025f; }
        const float* base = pr + (size_t)b * 7 * hw;
        float v0 = base[cell];
        float v1 = base[hw + cell];
        float v2 = base[2 * hw + cell];
        float v3 = base[3 * hw + cell];
        float v4 = base[4 * hw + cell];
        float gx = (float)(cell % W), gy = (float)(cell / W);
        float sx = 1.f / (1.f + expf(-v1));
        float sy = 1.f / (1.f + expf(-v2));
        g_pcx[i] = (sx + gx) * s;
        g_pcy[i] = (sy + gy) * s;
        float c3 = fminf(fmaxf(v3, -5.f), 5.f);
        float c4 = fminf(fmaxf(v4, -5.f), 5.f);
        g_pw[i] = expf(c3) * s;
        g_ph[i] = expf(c4) * s;
        // softplus(-v0), numerically stable
        float t = -v0;
        g_cls[i] = fmaxf(t, 0.f) + log1pf(expf(-fabsf(t)));
        g_obj[i] = 0.f; g_pm[i] = 0.f;
        g_b0[i] = 0.f; g_b1[i] = 0.f; g_b2[i] = 0.f; g_b3[i] = 0.f;
        g_f0[i] = 0.f; g_f1[i] = 0.f;
    }
}

// ---------------- assignment + loss kernel ----------------
__global__ __launch_bounds__(NTHREADS) void k_main(const float* __restrict__ p0s,
                                                   const float* __restrict__ p1s,
                                                   const float* __restrict__ p2s,
                                                   const float* __restrict__ tg) {
    __shared__ float s_tg[NGT * 7];
    __shared__ int   s_cnt;
    __shared__ int   s_lidx[CAP];
    __shared__ float s_liou[CAP];
    __shared__ float s_lcost[CAP];
    __shared__ float s_rf [NTHREADS];
    __shared__ float s_rf2[NTHREADS];
    __shared__ float s_rf3[NTHREADS];
    __shared__ int   s_ri [NTHREADS];
    __shared__ int   s_ri2[NTHREADS];
    __shared__ int   s_sel[10];
    __shared__ int   s_npos;

    int bx = blockIdx.x;
    int b = bx / 3, lev = bx % 3;
    int tid = threadIdx.x;

    int HW, W; float s; const float* pr; int off;
    if (lev == 0)      { HW = 25600; W = 160; s = 0.00625f; pr = p0s; off = 0; }
    else if (lev == 1) { HW = 6400;  W = 80;  s = 0.0125f;  pr = p1s; off = 25600; }
    else               { HW = 1600;  W = 40;  s = 0.025f;   pr = p2s; off = 32000; }
    const float* pb = pr + (size_t)b * 7 * HW;
    int gbase = b * CELLS_PER_B + off;

    for (int i = tid; i < NGT * 7; i += NTHREADS) s_tg[i] = tg[b * NGT * 7 + i];
    __syncthreads();

    int npos_cnt = 0;        // maintained exactly by thread 0
    float best_iou_t0 = 0.f; // thread-0-local

    for (int g = 0; g < NGT; ++g) {
        float cls = s_tg[g * 7 + 0];
        float cx = s_tg[g * 7 + 1], cy = s_tg[g * 7 + 2];
        float w  = s_tg[g * 7 + 3], h  = s_tg[g * 7 + 4];
        float fx = s_tg[g * 7 + 5], fy = s_tg[g * 7 + 6];
        float size = fmaxf(w, h) * 1280.f;
        bool valid = (cls == 0.f);
        if (lev == 0)      valid = valid && (size < 128.f);
        else if (lev == 1) valid = valid && (size >= 48.f && size < 288.f);
        else               valid = valid && (size >= 128.f);
        if (!valid) continue;   // uniform across block

        if (tid == 0) s_cnt = 0;
        __syncthreads();

        float cxg = cx / s, cyg = cy / s;
        float tx1 = cx - w * 0.5f, ty1 = cy - h * 0.5f;
        float tx2 = cx + w * 0.5f, ty2 = cy + h * 0.5f;
        float bxlo = tx1 / s, bxhi = tx2 / s, bylo = ty1 / s, byhi = ty2 / s;
        float ga = (tx2 - tx1) * (ty2 - ty1);

        // ---- pass 1: cand detection + compacted list + reductions ----
        float lsum = 0.f; int lnc = 0;
        float bdist = 3.4e38f; int bdidx = 0x7fffffff;
        for (int c = tid; c < HW; c += NTHREADS) {
            float gx = (float)(c % W), gy = (float)(c / W);
            float dx = gx - cxg, dy = gy - cyg;
            bool inc = (fabsf(dx) < 2.5f) && (fabsf(dy) < 2.5f);
            bool inb = (gx >= bxlo) && (gx < bxhi) && (gy >= bylo) && (gy < byhi);
            float dist = dx * dx + dy * dy;
            if (dist < bdist) { bdist = dist; bdidx = c; }
            if (inc || inb) {
                int gi = gbase + c;
                float iou = iou_cell(gi, tx1, ty1, tx2, ty2, ga);
                float cost = g_cls[gi] - 3.f * logf(iou + FEPS);
                lsum += iou; lnc++;
                int li = atomicAdd(&s_cnt, 1);
                if (li < CAP) { s_lidx[li] = c; s_liou[li] = iou; s_lcost[li] = cost; }
            }
        }
        s_rf[tid] = lsum; s_ri[tid] = lnc;
        s_rf2[tid] = bdist; s_ri2[tid] = bdidx;
        __syncthreads();
        for (int st = NTHREADS / 2; st > 0; st >>= 1) {
            if (tid < st) {
                s_rf[tid] += s_rf[tid + st];
                s_ri[tid] += s_ri[tid + st];
                float od = s_rf2[tid + st]; int oi = s_ri2[tid + st];
                if (od < s_rf2[tid] || (od == s_rf2[tid] && oi < s_ri2[tid])) {
                    s_rf2[tid] = od; s_ri2[tid] = oi;
                }
            }
            __syncthreads();
        }
        float iou_sum = s_rf[0];
        int   ncand   = s_ri[0];
        int   fbidx   = s_ri2[0];
        __syncthreads();   // protect smem before reuse

        if (ncand == 0) {
            // fallback: single nearest cell
            if (tid == 0) {
                int c = fbidx; int gi = gbase + c;
                float biou = iou_cell(gi, tx1, ty1, tx2, ty2, ga);
                if (g_pm[gi] == 0.f) { g_pm[gi] = 1.f; npos_cnt++; }
                g_obj[gi] = fmaxf(g_obj[gi], biou);
                g_b0[gi] = cxg - (float)(c % W);
                g_b1[gi] = cyg - (float)(c / W);
                g_b2[gi] = logf(w / s + FEPS);
                g_b3[gi] = logf(h / s + FEPS);
                g_f0[gi] = fx; g_f1[gi] = fy;
            }
        } else {
            int n_pos = (int)floorf(iou_sum);
            int mx = (ncand < 10) ? ncand : 10;
            if (n_pos < 1) n_pos = 1;
            if (n_pos > mx) n_pos = mx;
            int m = (ncand < CAP) ? ncand : CAP;

            for (int k = 0; k < n_pos; ++k) {
                float mc = 1e30f; int mi = 0x7fffffff; float miou = 0.f;
                for (int e = tid; e < m; e += NTHREADS) {
                    int ci = s_lidx[e];
                    bool used = false;
                    for (int q = 0; q < k; ++q) if (s_sel[q] == ci) { used = true; break; }
                    if (used) continue;
                    float cc = s_lcost[e];
                    if (cc < mc || (cc == mc && ci < mi)) { mc = cc; mi = ci; miou = s_liou[e]; }
                }
                s_rf[tid] = mc; s_ri[tid] = mi; s_rf2[tid] = miou;
                __syncthreads();
                for (int st = NTHREADS / 2; st > 0; st >>= 1) {
                    if (tid < st) {
                        float oc = s_rf[tid + st]; int oi = s_ri[tid + st];
                        if (oc < s_rf[tid] || (oc == s_rf[tid] && oi < s_ri[tid])) {
                            s_rf[tid] = oc; s_ri[tid] = oi; s_rf2[tid] = s_rf2[tid + st];
                        }
                    }
                    __syncthreads();
                }
                if (tid == 0) {
                    s_sel[k] = s_ri[0];
                    if (k == 0) best_iou_t0 = s_rf2[0];
                }
                __syncthreads();
            }
            if (tid == 0) {
                float lw = logf(w / s + FEPS);
                float lh = logf(h / s + FEPS);
                for (int k = 0; k < n_pos; ++k) {
                    int c = s_sel[k]; int gi = gbase + c;
                    if (g_pm[gi] == 0.f) { g_pm[gi] = 1.f; npos_cnt++; }
                    g_obj[gi] = fmaxf(g_obj[gi], best_iou_t0);
                    g_b0[gi] = cxg - (float)(c % W);
                    g_b1[gi] = cyg - (float)(c / W);
                    g_b2[gi] = lw; g_b3[gi] = lh;
                    g_f0[gi] = fx; g_f1[gi] = fy;
                }
            }
        }
        __syncthreads();
    }

    // ---- loss phase ----
    if (tid == 0) s_npos = npos_cnt;
    __syncthreads();
    float nposf = fmaxf((float)s_npos, 1.f);

    float objs = 0.f, boxs = 0.f, foots = 0.f;
    for (int c = tid; c < HW; c += NTHREADS) {
        int gi = gbase + c;
        float x = pb[c];
        float z = g_obj[gi];
        float ce = fmaxf(x, 0.f) - x * z + log1pf(expf(-fabsf(x)));
        float prob = 1.f / (1.f + expf(-x));
        float p_t = prob * z + (1.f - prob) * (1.f - z);
        float a_t = 0.25f * z + 0.75f * (1.f - z);
        float om = 1.f - p_t;
        objs += a_t * om * om * ce;
        float pm = g_pm[gi];
        if (pm > 0.f) {
            float gx = (float)(c % W), gy = (float)(c / W);
            float pcx = g_pcx[gi], pcy = g_pcy[gi], pw = g_pw[gi], ph = g_ph[gi];
            float tcx = (g_b0[gi] + gx) * s, tcy = (g_b1[gi] + gy) * s;
            float tw = expf(g_b2[gi]) * s, th = expf(g_b3[gi]) * s;
            float px1 = pcx - pw * 0.5f, py1 = pcy - ph * 0.5f;
            float px2 = pcx + pw * 0.5f, py2 = pcy + ph * 0.5f;
            float qx1 = tcx - tw * 0.5f, qy1 = tcy - th * 0.5f;
            float qx2 = tcx + tw * 0.5f, qy2 = tcy + th * 0.5f;
            float iw = fmaxf(fminf(px2, qx2) - fmaxf(px1, qx1), 0.f);
            float ih = fmaxf(fminf(py2, qy2) - fmaxf(py1, qy1), 0.f);
            float inter = iw * ih;
            float uni = pw * ph + tw * th - inter + FEPS;
            float iou = inter / uni;
            float rho2 = (pcx - tcx) * (pcx - tcx) + (pcy - tcy) * (pcy - tcy);
            float cw = fmaxf(px2, qx2) - fminf(px1, qx1);
            float ch = fmaxf(py2, qy2) - fminf(py1, qy1);
            float c2 = cw * cw + ch * ch + FEPS;
            float dv = atanf(tw / (th + FEPS)) - atanf(pw / (ph + FEPS));
            float v = 0.405284734569351f * dv * dv;   // 4/pi^2
            float alpha = v / (1.f - iou + v + FEPS);
            float ciou = iou - rho2 / c2 - alpha * v;
            boxs += pm * (1.f - ciou);
            float pf0 = 1.f / (1.f + expf(-pb[5 * HW + c]));
            float pf1 = 1.f / (1.f + expf(-pb[6 * HW + c]));
            float d0 = fabsf(pf0 - g_f0[gi]);
            float d1 = fabsf(pf1 - g_f1[gi]);
            float s0 = (d0 < 1.f) ? 0.5f * d0 * d0 : d0 - 0.5f;
            float s1 = (d1 < 1.f) ? 0.5f * d1 * d1 : d1 - 0.5f;
            foots += pm * (s0 + s1);
        }
    }
    s_rf[tid] = objs; s_rf2[tid] = boxs; s_rf3[tid] = foots;
    __syncthreads();
    for (int st = NTHREADS / 2; st > 0; st >>= 1) {
        if (tid < st) {
            s_rf[tid]  += s_rf[tid + st];
            s_rf2[tid] += s_rf2[tid + st];
            s_rf3[tid] += s_rf3[tid + st];
        }
        __syncthreads();
    }
    if (tid == 0) {
        double contrib = ((double)s_rf[0] / (double)HW +
                          (5.0 * (double)s_rf2[0] + (double)s_rf3[0]) / (double)nposf) / 64.0;
        atomicAdd(&g_acc, contrib);
    }
}

__global__ void k_fin(float* out) {
    out[0] = (float)g_acc;
}

extern "C" void kernel_launch(void* const* d_in, const int* in_sizes, int n_in,
                              void* d_out, int out_size) {
    const float* p0 = (const float*)d_in[0];
    const float* p1 = (const float*)d_in[1];
    const float* p2 = (const float*)d_in[2];
    const float* tg = (const float*)d_in[3];
    k_pre<<<1024, NTHREADS>>>(p0, p1, p2);
    k_main<<<BATCH * 3, NTHREADS>>>(p0, p1, p2, tg);
    k_fin<<<1, 1>>>((float*)d_out);
}

// round 2
// speedup vs baseline: 2.8758x; 2.8758x over previous
#include <cuda_runtime.h>
#include <math.h>

#define BATCH 64
#define NGT 40
#define CELLS_PER_B 33600   // 160*160 + 80*80 + 40*40
#define TOTC (BATCH*CELLS_PER_B)
#define CAP 512             // max candidates per GT (region bounded ~441)
#define TCAP 400            // max assigned cells per (b,lev) = 40 GT * 10
#define FEPS 1e-7f
#define MT 128

__device__ double g_acc;

__global__ void k_init() { g_acc = 0.0; }

// focal obj term at z=0 (fast intrinsics; consistent with correction kernel)
__device__ __forceinline__ float obj0(float x) {
    float e = __expf(-fabsf(x));
    float sp = fmaxf(x, 0.f) + __logf(1.f + e);         // softplus(x) = BCE(z=0)
    float prob = (x >= 0.f) ? 1.f / (1.f + e) : e / (1.f + e);
    return 0.75f * prob * prob * sp;
}

__global__ __launch_bounds__(256) void k_obj(const float* __restrict__ p0,
                                             const float* __restrict__ p1,
                                             const float* __restrict__ p2) {
    int idx = blockIdx.x * 256 + threadIdx.x;
    int nth = gridDim.x * 256;
    float acc = 0.f;
    for (int i = idx; i < TOTC; i += nth) {
        int b = i / CELLS_PER_B;
        int r = i - b * CELLS_PER_B;
        const float* pr; int hw, cell; float invhw;
        if (r < 25600)      { pr = p0; hw = 25600; cell = r;         invhw = 1.f / 25600.f; }
        else if (r < 32000) { pr = p1; hw = 6400;  cell = r - 25600; invhw = 1.f / 6400.f; }
        else                { pr = p2; hw = 1600;  cell = r - 32000; invhw = 1.f / 1600.f; }
        acc += obj0(pr[(size_t)b * 7 * hw + cell]) * invhw;
    }
    __shared__ float sh[8];
    for (int o = 16; o; o >>= 1) acc += __shfl_down_sync(0xffffffffu, acc, o);
    if ((threadIdx.x & 31) == 0) sh[threadIdx.x >> 5] = acc;
    __syncthreads();
    if (threadIdx.x == 0) {
        float t = 0.f;
        for (int w = 0; w < 8; w++) t += sh[w];
        atomicAdd(&g_acc, (double)t / 64.0);
    }
}

__device__ __forceinline__ int nearest_idx(float t, int n) {
    float f = floorf(t);
    int i = (int)f;
    if (i < 0) return 0;
    if (i >= n - 1) return n - 1;
    float d1 = t - f, d2 = (f + 1.f) - t;
    return (d2 < d1) ? i + 1 : i;   // tie -> lower index
}

__global__ __launch_bounds__(MT) void k_main(const float* __restrict__ p0,
                                             const float* __restrict__ p1,
                                             const float* __restrict__ p2,
                                             const float* __restrict__ tg) {
    __shared__ float s_tg[NGT * 7];
    __shared__ int   s_cnt;
    __shared__ int   s_lidx[CAP];
    __shared__ float s_liou[CAP];
    __shared__ float s_lcost[CAP];
    __shared__ int   s_tcell[TCAP];
    __shared__ float s_tobj[TCAP], s_tb0[TCAP], s_tb1[TCAP], s_tb2[TCAP], s_tb3[TCAP];
    __shared__ float s_tf0[TCAP], s_tf1[TCAP];
    __shared__ int   s_tcnt;
    __shared__ float s_wf[4]; __shared__ int s_wi[4]; __shared__ float s_wu[4];
    __shared__ int   s_sel[10];
    __shared__ float s_selio;
    __shared__ int   s_npos;

    int tid = threadIdx.x;
    int b = blockIdx.x / 3, lev = blockIdx.x - 3 * b;
    int HW, W; float s; const float* pr;
    if (lev == 0)      { HW = 25600; W = 160; s = 0.00625f; pr = p0; }
    else if (lev == 1) { HW = 6400;  W = 80;  s = 0.0125f;  pr = p1; }
    else               { HW = 1600;  W = 40;  s = 0.025f;   pr = p2; }
    const float* pb = pr + (size_t)b * 7 * HW;

    for (int i = tid; i < NGT * 7; i += MT) s_tg[i] = tg[b * NGT * 7 + i];
    if (tid == 0) s_tcnt = 0;
    __syncthreads();

    for (int g = 0; g < NGT; ++g) {
        float cls = s_tg[g * 7], cx = s_tg[g * 7 + 1], cy = s_tg[g * 7 + 2];
        float w = s_tg[g * 7 + 3], h = s_tg[g * 7 + 4];
        float fx = s_tg[g * 7 + 5], fy = s_tg[g * 7 + 6];
        float size = fmaxf(w, h) * 1280.f;
        bool valid = (cls == 0.f);
        if (lev == 0)      valid = valid && (size < 128.f);
        else if (lev == 1) valid = valid && (size >= 48.f && size < 288.f);
        else               valid = valid && (size >= 128.f);
        if (!valid) continue;   // uniform across block

        if (tid == 0) s_cnt = 0;
        __syncthreads();

        float cxg = cx / s, cyg = cy / s;
        float tx1 = cx - w * 0.5f, ty1 = cy - h * 0.5f;
        float tx2 = cx + w * 0.5f, ty2 = cy + h * 0.5f;
        float bxlo = tx1 / s, bxhi = tx2 / s, bylo = ty1 / s, byhi = ty2 / s;
        float ga = (tx2 - tx1) * (ty2 - ty1);

        // candidate region (superset of in_center | in_box, clamped to grid)
        int x0 = (int)floorf(fminf(cxg - 2.5f, bxlo)); if (x0 < 0) x0 = 0;
        int x1 = (int)ceilf (fmaxf(cxg + 2.5f, bxhi)); if (x1 > W - 1) x1 = W - 1;
        int y0 = (int)floorf(fminf(cyg - 2.5f, bylo)); if (y0 < 0) y0 = 0;
        int y1 = (int)ceilf (fmaxf(cyg + 2.5f, byhi)); if (y1 > W - 1) y1 = W - 1;
        int rw = x1 - x0 + 1, rh = y1 - y0 + 1;
        int rn = (rw > 0 && rh > 0) ? rw * rh : 0;

        float lsum = 0.f;
        for (int i = tid; i < rn; i += MT) {
            int gxi = x0 + i % rw, gyi = y0 + i / rw;
            float gx = (float)gxi, gy = (float)gyi;
            bool inc = (fabsf(gx - cxg) < 2.5f) && (fabsf(gy - cyg) < 2.5f);
            bool inb = (gx >= bxlo) && (gx < bxhi) && (gy >= bylo) && (gy < byhi);
            if (inc || inb) {
                int cell = gyi * W + gxi;
                float v1 = pb[HW + cell], v2 = pb[2 * HW + cell];
                float v3 = pb[3 * HW + cell], v4 = pb[4 * HW + cell];
                float pcx = (1.f / (1.f + expf(-v1)) + gx) * s;
                float pcy = (1.f / (1.f + expf(-v2)) + gy) * s;
                float pw = expf(fminf(fmaxf(v3, -5.f), 5.f)) * s;
                float ph = expf(fminf(fmaxf(v4, -5.f), 5.f)) * s;
                float px1 = pcx - pw * 0.5f, py1 = pcy - ph * 0.5f;
                float px2 = pcx + pw * 0.5f, py2 = pcy + ph * 0.5f;
                float iw = fmaxf(fminf(px2, tx2) - fmaxf(px1, tx1), 0.f);
                float ih = fmaxf(fminf(py2, ty2) - fmaxf(py1, ty1), 0.f);
                float inter = iw * ih;
                float aa = (px2 - px1) * (py2 - py1);
                float iou = inter / (aa + ga - inter + FEPS);
                float v0 = pb[cell];
                float t = -v0;
                float cc = fmaxf(t, 0.f) + log1pf(expf(-fabsf(t))) - 3.f * logf(iou + FEPS);
                lsum += iou;
                int li = atomicAdd(&s_cnt, 1);
                if (li < CAP) { s_lidx[li] = cell; s_liou[li] = iou; s_lcost[li] = cc; }
            }
        }
        for (int o = 16; o; o >>= 1) lsum += __shfl_down_sync(0xffffffffu, lsum, o);
        if ((tid & 31) == 0) s_wf[tid >> 5] = lsum;
        __syncthreads();
        int ncand = s_cnt;
        if (tid == 0) {
            if (ncand == 0) {
                // analytic argmin-dist fallback (in practice unreachable)
                int nx = nearest_idx(cxg, W), ny = nearest_idx(cyg, W);
                int cell = ny * W + nx;
                float gx = (float)nx, gy = (float)ny;
                float v1 = pb[HW + cell], v2 = pb[2 * HW + cell];
                float v3 = pb[3 * HW + cell], v4 = pb[4 * HW + cell];
                float pcx = (1.f / (1.f + expf(-v1)) + gx) * s;
                float pcy = (1.f / (1.f + expf(-v2)) + gy) * s;
                float pw = expf(fminf(fmaxf(v3, -5.f), 5.f)) * s;
                float ph = expf(fminf(fmaxf(v4, -5.f), 5.f)) * s;
                float px1 = pcx - pw * 0.5f, py1 = pcy - ph * 0.5f;
                float px2 = pcx + pw * 0.5f, py2 = pcy + ph * 0.5f;
                float iw = fmaxf(fminf(px2, tx2) - fmaxf(px1, tx1), 0.f);
                float ih = fmaxf(fminf(py2, ty2) - fmaxf(py1, ty1), 0.f);
                float inter = iw * ih;
                float aa = (px2 - px1) * (py2 - py1);
                s_sel[0] = cell;
                s_selio = inter / (aa + ga - inter + FEPS);
                s_npos = 1;
            } else {
                float su = s_wf[0] + s_wf[1] + s_wf[2] + s_wf[3];
                int np = (int)floorf(su);
                int mx = ncand < 10 ? ncand : 10;
                if (np < 1) np = 1;
                if (np > mx) np = mx;
                s_npos = np;
            }
        }
        __syncthreads();
        int n_pos = s_npos;
        int m = ncand < CAP ? ncand : CAP;
        if (ncand > 0) {
            for (int k = 0; k < n_pos; ++k) {
                float mc = 3.4e38f; int mi = 0x7fffffff; float mu = 0.f;
                for (int e = tid; e < m; e += MT) {
                    int ci = s_lidx[e];
                    bool used = false;
                    for (int q = 0; q < k; ++q) if (s_sel[q] == ci) { used = true; break; }
                    if (used) continue;
                    float cc = s_lcost[e];
                    if (cc < mc || (cc == mc && ci < mi)) { mc = cc; mi = ci; mu = s_liou[e]; }
                }
                for (int o = 16; o; o >>= 1) {
                    float oc = __shfl_down_sync(0xffffffffu, mc, o);
                    int   oi = __shfl_down_sync(0xffffffffu, mi, o);
                    float ou = __shfl_down_sync(0xffffffffu, mu, o);
                    if (oc < mc || (oc == mc && oi < mi)) { mc = oc; mi = oi; mu = ou; }
                }
                if ((tid & 31) == 0) { int wd = tid >> 5; s_wf[wd] = mc; s_wi[wd] = mi; s_wu[wd] = mu; }
                __syncthreads();
                if (tid == 0) {
                    float bc = s_wf[0]; int bi = s_wi[0]; float bu = s_wu[0];
                    for (int w2 = 1; w2 < 4; w2++)
                        if (s_wf[w2] < bc || (s_wf[w2] == bc && s_wi[w2] < bi)) {
                            bc = s_wf[w2]; bi = s_wi[w2]; bu = s_wu[w2];
                        }
                    s_sel[k] = bi;
                    if (k == 0) s_selio = bu;
                }
                __syncthreads();
            }
        }
        // sparse target table update (overwrite semantics; thread 0 serial)
        if (tid == 0) {
            float lw = logf(w / s + FEPS), lh = logf(h / s + FEPS);
            float bio = s_selio;
            for (int k = 0; k < n_pos; ++k) {
                int c = s_sel[k];
                int e = -1;
                for (int q = 0; q < s_tcnt; ++q) if (s_tcell[q] == c) { e = q; break; }
                if (e < 0) { e = s_tcnt++; s_tcell[e] = c; s_tobj[e] = bio; }
                else s_tobj[e] = fmaxf(s_tobj[e], bio);
                s_tb0[e] = cxg - (float)(c % W);
                s_tb1[e] = cyg - (float)(c / W);
                s_tb2[e] = lw; s_tb3[e] = lh;
                s_tf0[e] = fx; s_tf1[e] = fy;
            }
        }
        __syncthreads();
    }

    // ---- sparse loss: obj corrections + box + foot over assigned cells ----
    int tcnt = s_tcnt;
    float od = 0.f, bs = 0.f, fs = 0.f;
    for (int e = tid; e < tcnt; e += MT) {
        int c = s_tcell[e]; float z = s_tobj[e];
        float x = pb[c];
        float eab = __expf(-fabsf(x));
        float l1p = __logf(1.f + eab);
        float prob = (x >= 0.f) ? 1.f / (1.f + eab) : eab / (1.f + eab);
        float ce0 = fmaxf(x, 0.f) + l1p;
        float t0 = 0.75f * prob * prob * ce0;           // matches k_obj's per-cell term
        float ce = ce0 - x * z;
        float pt = prob * z + (1.f - prob) * (1.f - z);
        float at = 0.25f * z + 0.75f * (1.f - z);
        float om = 1.f - pt;
        od += at * om * om * ce - t0;

        int gxi = c % W, gyi = c / W;
        float gx = (float)gxi, gy = (float)gyi;
        float v1 = pb[HW + c], v2 = pb[2 * HW + c], v3 = pb[3 * HW + c], v4 = pb[4 * HW + c];
        float pcx = (1.f / (1.f + expf(-v1)) + gx) * s;
        float pcy = (1.f / (1.f + expf(-v2)) + gy) * s;
        float pw = expf(fminf(fmaxf(v3, -5.f), 5.f)) * s;
        float ph = expf(fminf(fmaxf(v4, -5.f), 5.f)) * s;
        float tcx = (s_tb0[e] + gx) * s, tcy = (s_tb1[e] + gy) * s;
        float tw = expf(s_tb2[e]) * s, th = expf(s_tb3[e]) * s;
        float px1 = pcx - pw * 0.5f, py1 = pcy - ph * 0.5f;
        float px2 = pcx + pw * 0.5f, py2 = pcy + ph * 0.5f;
        float qx1 = tcx - tw * 0.5f, qy1 = tcy - th * 0.5f;
        float qx2 = tcx + tw * 0.5f, qy2 = tcy + th * 0.5f;
        float iw = fmaxf(fminf(px2, qx2) - fmaxf(px1, qx1), 0.f);
        float ih = fmaxf(fminf(py2, qy2) - fmaxf(py1, qy1), 0.f);
        float inter = iw * ih;
        float uni = pw * ph + tw * th - inter + FEPS;
        float iou = inter / uni;
        float rho2 = (pcx - tcx) * (pcx - tcx) + (pcy - tcy) * (pcy - tcy);
        float cw2 = fmaxf(px2, qx2) - fminf(px1, qx1);
        float ch2 = fmaxf(py2, qy2) - fminf(py1, qy1);
        float c2 = cw2 * cw2 + ch2 * ch2 + FEPS;
        float dv = atanf(tw / (th + FEPS)) - atanf(pw / (ph + FEPS));
        float v = 0.405284734569351f * dv * dv;          // 4/pi^2
        float alpha = v / (1.f - iou + v + FEPS);
        float ciou = iou - rho2 / c2 - alpha * v;
        bs += 1.f - ciou;

        float pf0 = 1.f / (1.f + expf(-pb[5 * HW + c]));
        float pf1 = 1.f / (1.f + expf(-pb[6 * HW + c]));
        float d0 = fabsf(pf0 - s_tf0[e]);
        float d1 = fabsf(pf1 - s_tf1[e]);
        fs += ((d0 < 1.f) ? 0.5f * d0 * d0 : d0 - 0.5f)
            + ((d1 < 1.f) ? 0.5f * d1 * d1 : d1 - 0.5f);
    }
    for (int o = 16; o; o >>= 1) {
        od += __shfl_down_sync(0xffffffffu, od, o);
        bs += __shfl_down_sync(0xffffffffu, bs, o);
        fs += __shfl_down_sync(0xffffffffu, fs, o);
    }
    __shared__ float s_od[4], s_bs[4], s_fs[4];
    if ((tid & 31) == 0) { int w2 = tid >> 5; s_od[w2] = od; s_bs[w2] = bs; s_fs[w2] = fs; }
    __syncthreads();
    if (tid == 0) {
        float O = s_od[0] + s_od[1] + s_od[2] + s_od[3];
        float Bx = s_bs[0] + s_bs[1] + s_bs[2] + s_bs[3];
        float F = s_fs[0] + s_fs[1] + s_fs[2] + s_fs[3];
        double npos = (tcnt > 0) ? (double)tcnt : 1.0;
        double contrib = ((double)O / (double)HW + (5.0 * (double)Bx + (double)F) / npos) / 64.0;
        atomicAdd(&g_acc, contrib);
    }
}

__global__ void k_fin(float* out) { out[0] = (float)g_acc; }

extern "C" void kernel_launch(void* const* d_in, const int* in_sizes, int n_in,
                              void* d_out, int out_size) {
    const float* p0 = (const float*)d_in[0];
    const float* p1 = (const float*)d_in[1];
    const float* p2 = (const float*)d_in[2];
    const float* tg = (const float*)d_in[3];
    k_init<<<1, 1>>>();
    k_obj<<<1184, 256>>>(p0, p1, p2);
    k_main<<<BATCH * 3, MT>>>(p0, p1, p2, tg);
    k_fin<<<1, 1>>>((float*)d_out);
}

// round 3
// speedup vs baseline: 10.8231x; 3.7635x over previous
#include <cuda_runtime.h>
#include <math.h>

#define BATCH 64
#define NGT 40
#define CELLS_PER_B 33600   // 160*160 + 80*80 + 40*40
#define TOTC (BATCH*CELLS_PER_B)
#define CAP 512
#define FEPS 1e-7f
#define NASSIGN (BATCH*3*10)    // 1920 assign blocks (4 warps each -> 40 GTs)
#define NOBJ 1184               // obj partial-sum blocks
#define NB2 (BATCH*3)           // 192 merge/loss blocks
#define NUNIT (BATCH*3*NGT)     // 7680 (b,lev,gt) units
#define EMAX (NGT*10)           // 400 max entries per (b,lev)

// ---- static device scratch ----
__device__ int    A_nsel[NUNIT];
__device__ float  A_biou[NUNIT];
__device__ int    A_cell[NUNIT*10];
__device__ float  g_pobj[NOBJ];     // per-block write-only slots (no init needed)
__device__ double g_ploss[NB2];

// focal obj term at z=0 (fast intrinsics; must match correction in k2)
__device__ __forceinline__ float obj0(float x) {
    float e = __expf(-fabsf(x));
    float sp = fmaxf(x, 0.f) + __logf(1.f + e);
    float prob = (x >= 0.f) ? 1.f / (1.f + e) : e / (1.f + e);
    return 0.75f * prob * prob * sp;
}

__device__ __forceinline__ int nearest_idx(float t, int n) {
    float f = floorf(t);
    int i = (int)f;
    if (i < 0) return 0;
    if (i >= n - 1) return n - 1;
    float d1 = t - f, d2 = (f + 1.f) - t;
    return (d2 < d1) ? i + 1 : i;   // tie -> lower index
}

// ================= k1: fused per-GT assignment (warp/GT) + dense obj partials ==============
__global__ __launch_bounds__(128) void k1(const float* __restrict__ p0,
                                          const float* __restrict__ p1,
                                          const float* __restrict__ p2,
                                          const float* __restrict__ tg) {
    int tid = threadIdx.x;

    if (blockIdx.x >= NASSIGN) {
        // ---- obj role: z=0 focal loss partial sums ----
        __shared__ float sh[4];
        int obid = blockIdx.x - NASSIGN;
        int idx = obid * 128 + tid;
        float acc = 0.f;
        for (int i = idx; i < TOTC; i += NOBJ * 128) {
            int b = i / CELLS_PER_B;
            int r = i - b * CELLS_PER_B;
            const float* pr; int hw, cell; float invhw;
            if (r < 25600)      { pr = p0; hw = 25600; cell = r;         invhw = 1.f / 25600.f; }
            else if (r < 32000) { pr = p1; hw = 6400;  cell = r - 25600; invhw = 1.f / 6400.f; }
            else                { pr = p2; hw = 1600;  cell = r - 32000; invhw = 1.f / 1600.f; }
            acc += obj0(pr[(size_t)b * 7 * hw + cell]) * invhw;
        }
        for (int o = 16; o; o >>= 1) acc += __shfl_down_sync(0xffffffffu, acc, o);
        if ((tid & 31) == 0) sh[tid >> 5] = acc;
        __syncthreads();
        if (tid == 0) g_pobj[obid] = sh[0] + sh[1] + sh[2] + sh[3];
        return;
    }

    // ---- assign role: one warp per GT, no block barriers ----
    __shared__ int   s_idx[4][CAP];
    __shared__ float s_iou[4][CAP];
    __shared__ float s_cst[4][CAP];
    __shared__ int   s_sel[4][10];

    int bid = blockIdx.x;
    int b = bid / 30, rr = bid % 30;
    int lev = rr / 10, chunk = rr % 10;
    int wid = tid >> 5, lane = tid & 31;
    int g = chunk * 4 + wid;
    int u = (b * 3 + lev) * NGT + g;

    const float* tb = tg + (b * NGT + g) * 7;
    float cls = tb[0], cx = tb[1], cy = tb[2], w = tb[3], h = tb[4];
    float size = fmaxf(w, h) * 1280.f;
    bool valid = (cls == 0.f);
    int HW, W; float s; const float* pr;
    if (lev == 0)      { HW = 25600; W = 160; s = 0.00625f; pr = p0; valid = valid && (size < 128.f); }
    else if (lev == 1) { HW = 6400;  W = 80;  s = 0.0125f;  pr = p1; valid = valid && (size >= 48.f && size < 288.f); }
    else               { HW = 1600;  W = 40;  s = 0.025f;   pr = p2; valid = valid && (size >= 128.f); }
    if (!valid) { if (lane == 0) A_nsel[u] = 0; return; }
    const float* pb = pr + (size_t)b * 7 * HW;

    float cxg = cx / s, cyg = cy / s;
    float tx1 = cx - w * 0.5f, ty1 = cy - h * 0.5f;
    float tx2 = cx + w * 0.5f, ty2 = cy + h * 0.5f;
    float bxlo = tx1 / s, bxhi = tx2 / s, bylo = ty1 / s, byhi = ty2 / s;
    float ga = (tx2 - tx1) * (ty2 - ty1);

    int x0 = (int)floorf(fminf(cxg - 2.5f, bxlo)); if (x0 < 0) x0 = 0;
    int x1 = (int)ceilf (fmaxf(cxg + 2.5f, bxhi)); if (x1 > W - 1) x1 = W - 1;
    int y0 = (int)floorf(fminf(cyg - 2.5f, bylo)); if (y0 < 0) y0 = 0;
    int y1 = (int)ceilf (fmaxf(cyg + 2.5f, byhi)); if (y1 > W - 1) y1 = W - 1;
    int rw = x1 - x0 + 1, rh = y1 - y0 + 1;
    int rn = (rw > 0 && rh > 0) ? rw * rh : 0;

    float lsum = 0.f;
    int cnt = 0;
    for (int base = 0; base < rn; base += 32) {
        int i = base + lane;
        bool act = i < rn;
        int gxi = 0, gyi = 0; float iou = 0.f, cc = 0.f; bool cand = false;
        if (act) {
            gxi = x0 + i % rw; gyi = y0 + i / rw;
            float gx = (float)gxi, gy = (float)gyi;
            bool inc = (fabsf(gx - cxg) < 2.5f) && (fabsf(gy - cyg) < 2.5f);
            bool inb = (gx >= bxlo) && (gx < bxhi) && (gy >= bylo) && (gy < byhi);
            cand = inc || inb;
            if (cand) {
                int cell = gyi * W + gxi;
                float v1 = pb[HW + cell], v2 = pb[2 * HW + cell];
                float v3 = pb[3 * HW + cell], v4 = pb[4 * HW + cell];
                float pcx = (1.f / (1.f + expf(-v1)) + gx) * s;
                float pcy = (1.f / (1.f + expf(-v2)) + gy) * s;
                float pw = expf(fminf(fmaxf(v3, -5.f), 5.f)) * s;
                float ph = expf(fminf(fmaxf(v4, -5.f), 5.f)) * s;
                float px1 = pcx - pw * 0.5f, py1 = pcy - ph * 0.5f;
                float px2 = pcx + pw * 0.5f, py2 = pcy + ph * 0.5f;
                float iw = fmaxf(fminf(px2, tx2) - fmaxf(px1, tx1), 0.f);
                float ih = fmaxf(fminf(py2, ty2) - fmaxf(py1, ty1), 0.f);
                float inter = iw * ih;
                float aa = (px2 - px1) * (py2 - py1);
                iou = inter / (aa + ga - inter + FEPS);
                float v0 = pb[cell];
                float t = -v0;
                cc = fmaxf(t, 0.f) + log1pf(expf(-fabsf(t))) - 3.f * logf(iou + FEPS);
            }
        }
        unsigned mvote = __ballot_sync(0xffffffffu, cand);
        if (cand) {
            int li = cnt + __popc(mvote & ((1u << lane) - 1u));
            if (li < CAP) { s_idx[wid][li] = gyi * W + gxi; s_iou[wid][li] = iou; s_cst[wid][li] = cc; }
            lsum += iou;
        }
        cnt += __popc(mvote);
    }
    for (int o = 16; o; o >>= 1) lsum += __shfl_xor_sync(0xffffffffu, lsum, o);
    int ncand = cnt;
    __syncwarp();

    if (ncand == 0) {
        if (lane == 0) {
            int nx = nearest_idx(cxg, W), ny = nearest_idx(cyg, W);
            int cell = ny * W + nx;
            float gx = (float)nx, gy = (float)ny;
            float v1 = pb[HW + cell], v2 = pb[2 * HW + cell];
            float v3 = pb[3 * HW + cell], v4 = pb[4 * HW + cell];
            float pcx = (1.f / (1.f + expf(-v1)) + gx) * s;
            float pcy = (1.f / (1.f + expf(-v2)) + gy) * s;
            float pw = expf(fminf(fmaxf(v3, -5.f), 5.f)) * s;
            float ph = expf(fminf(fmaxf(v4, -5.f), 5.f)) * s;
            float px1 = pcx - pw * 0.5f, py1 = pcy - ph * 0.5f;
            float px2 = pcx + pw * 0.5f, py2 = pcy + ph * 0.5f;
            float iw = fmaxf(fminf(px2, tx2) - fmaxf(px1, tx1), 0.f);
            float ih = fmaxf(fminf(py2, ty2) - fmaxf(py1, ty1), 0.f);
            float inter = iw * ih;
            float aa = (px2 - px1) * (py2 - py1);
            A_nsel[u] = 1;
            A_biou[u] = inter / (aa + ga - inter + FEPS);
            A_cell[u * 10] = cell;
        }
        return;
    }

    int np = (int)floorf(lsum);
    int mx = ncand < 10 ? ncand : 10;
    if (np < 1) np = 1;
    if (np > mx) np = mx;
    int m = ncand < CAP ? ncand : CAP;

    float bio = 0.f;
    for (int k = 0; k < np; ++k) {
        float mc = 3.4e38f; int mi = 0x7fffffff; float mu = 0.f;
        for (int e = lane; e < m; e += 32) {
            int ci = s_idx[wid][e];
            bool used = false;
            for (int q = 0; q < k; ++q) if (s_sel[wid][q] == ci) { used = true; break; }
            if (used) continue;
            float cc = s_cst[wid][e];
            if (cc < mc || (cc == mc && ci < mi)) { mc = cc; mi = ci; mu = s_iou[wid][e]; }
        }
        for (int o = 16; o; o >>= 1) {
            float oc = __shfl_xor_sync(0xffffffffu, mc, o);
            int   oi = __shfl_xor_sync(0xffffffffu, mi, o);
            float ou = __shfl_xor_sync(0xffffffffu, mu, o);
            if (oc < mc || (oc == mc && oi < mi)) { mc = oc; mi = oi; mu = ou; }
        }
        if (lane == 0) s_sel[wid][k] = mi;
        if (k == 0) bio = mu;
        __syncwarp();
    }
    if (lane == 0) {
        A_nsel[u] = np;
        A_biou[u] = bio;
        for (int k = 0; k < np; ++k) A_cell[u * 10 + k] = s_sel[wid][k];
    }
}

// ================= k2: per-(b,lev) merge (overwrite semantics) + sparse loss ==============
__global__ __launch_bounds__(128) void k2(const float* __restrict__ p0,
                                          const float* __restrict__ p1,
                                          const float* __restrict__ p2,
                                          const float* __restrict__ tg) {
    __shared__ float s_tg[NGT * 7];
    __shared__ int   s_off[NGT + 1];
    __shared__ int   e_cell[EMAX];
    __shared__ int   e_g[EMAX];
    __shared__ float e_iou[EMAX];
    __shared__ float s_od[4], s_bs[4], s_fs[4];
    __shared__ int   s_np[4];

    int bid = blockIdx.x;
    int b = bid / 3, lev = bid % 3;
    int tid = threadIdx.x;
    int HW, W; float s; const float* pr;
    if (lev == 0)      { HW = 25600; W = 160; s = 0.00625f; pr = p0; }
    else if (lev == 1) { HW = 6400;  W = 80;  s = 0.0125f;  pr = p1; }
    else               { HW = 1600;  W = 40;  s = 0.025f;   pr = p2; }
    const float* pb = pr + (size_t)b * 7 * HW;

    for (int i = tid; i < NGT * 7; i += 128) s_tg[i] = tg[b * NGT * 7 + i];
    if (tid == 0) {
        int o = 0;
        for (int g = 0; g < NGT; ++g) { s_off[g] = o; o += A_nsel[bid * NGT + g]; }
        s_off[NGT] = o;
    }
    __syncthreads();
    int tcnt = s_off[NGT];

    for (int t = tid; t < NGT * 10; t += 128) {
        int g = t / 10, k = t % 10;
        int ns = s_off[g + 1] - s_off[g];
        if (k < ns) {
            int u = bid * NGT + g;
            int e = s_off[g] + k;
            e_cell[e] = A_cell[u * 10 + k];
            e_g[e] = g;
            e_iou[e] = A_biou[u];
        }
    }
    __syncthreads();

    float od = 0.f, bs = 0.f, fs = 0.f;
    int np = 0;
    for (int e = tid; e < tcnt; e += 128) {
        int c = e_cell[e], ge = e_g[e];
        float z = e_iou[e];
        bool win = true;
        for (int e2 = 0; e2 < tcnt; ++e2) {
            if (e2 == e) continue;
            if (e_cell[e2] == c) {
                z = fmaxf(z, e_iou[e2]);
                if (e_g[e2] > ge) win = false;
            }
        }
        if (!win) continue;
        np++;

        // obj correction: focal(x,z) - focal(x,0)
        float x = pb[c];
        float eab = __expf(-fabsf(x));
        float l1p = __logf(1.f + eab);
        float prob = (x >= 0.f) ? 1.f / (1.f + eab) : eab / (1.f + eab);
        float ce0 = fmaxf(x, 0.f) + l1p;
        float t0 = 0.75f * prob * prob * ce0;
        float ce = ce0 - x * z;
        float pt = prob * z + (1.f - prob) * (1.f - z);
        float at = 0.25f * z + 0.75f * (1.f - z);
        float om = 1.f - pt;
        od += at * om * om * ce - t0;

        // targets from winner g
        float cx = s_tg[ge * 7 + 1], cy = s_tg[ge * 7 + 2];
        float w = s_tg[ge * 7 + 3], h = s_tg[ge * 7 + 4];
        float fx = s_tg[ge * 7 + 5], fy = s_tg[ge * 7 + 6];
        float cxg = cx / s, cyg = cy / s;
        int gxi = c % W, gyi = c / W;
        float gx = (float)gxi, gy = (float)gyi;
        float tb0 = cxg - gx, tb1 = cyg - gy;
        float lw = logf(w / s + FEPS), lh = logf(h / s + FEPS);

        float v1 = pb[HW + c], v2 = pb[2 * HW + c], v3 = pb[3 * HW + c], v4 = pb[4 * HW + c];
        float pcx = (1.f / (1.f + expf(-v1)) + gx) * s;
        float pcy = (1.f / (1.f + expf(-v2)) + gy) * s;
        float pw = expf(fminf(fmaxf(v3, -5.f), 5.f)) * s;
        float ph = expf(fminf(fmaxf(v4, -5.f), 5.f)) * s;
        float tcx = (tb0 + gx) * s, tcy = (tb1 + gy) * s;
        float tw = expf(lw) * s, th = expf(lh) * s;
        float px1 = pcx - pw * 0.5f, py1 = pcy - ph * 0.5f;
        float px2 = pcx + pw * 0.5f, py2 = pcy + ph * 0.5f;
        float qx1 = tcx - tw * 0.5f, qy1 = tcy - th * 0.5f;
        float qx2 = tcx + tw * 0.5f, qy2 = tcy + th * 0.5f;
        float iw = fmaxf(fminf(px2, qx2) - fmaxf(px1, qx1), 0.f);
        float ih = fmaxf(fminf(py2, qy2) - fmaxf(py1, qy1), 0.f);
        float inter = iw * ih;
        float uni = pw * ph + tw * th - inter + FEPS;
        float iou = inter / uni;
        float rho2 = (pcx - tcx) * (pcx - tcx) + (pcy - tcy) * (pcy - tcy);
        float cw2 = fmaxf(px2, qx2) - fminf(px1, qx1);
        float ch2 = fmaxf(py2, qy2) - fminf(py1, qy1);
        float c2 = cw2 * cw2 + ch2 * ch2 + FEPS;
        float dv = atanf(tw / (th + FEPS)) - atanf(pw / (ph + FEPS));
        float v = 0.405284734569351f * dv * dv;          // 4/pi^2
        float alpha = v / (1.f - iou + v + FEPS);
        float ciou = iou - rho2 / c2 - alpha * v;
        bs += 1.f - ciou;

        float pf0 = 1.f / (1.f + expf(-pb[5 * HW + c]));
        float pf1 = 1.f / (1.f + expf(-pb[6 * HW + c]));
        float d0 = fabsf(pf0 - fx);
        float d1 = fabsf(pf1 - fy);
        fs += ((d0 < 1.f) ? 0.5f * d0 * d0 : d0 - 0.5f)
            + ((d1 < 1.f) ? 0.5f * d1 * d1 : d1 - 0.5f);
    }
    for (int o = 16; o; o >>= 1) {
        od += __shfl_down_sync(0xffffffffu, od, o);
        bs += __shfl_down_sync(0xffffffffu, bs, o);
        fs += __shfl_down_sync(0xffffffffu, fs, o);
        np += __shfl_down_sync(0xffffffffu, np, o);
    }
    if ((tid & 31) == 0) { int w2 = tid >> 5; s_od[w2] = od; s_bs[w2] = bs; s_fs[w2] = fs; s_np[w2] = np; }
    __syncthreads();
    if (tid == 0) {
        float O = s_od[0] + s_od[1] + s_od[2] + s_od[3];
        float Bx = s_bs[0] + s_bs[1] + s_bs[2] + s_bs[3];
        float F = s_fs[0] + s_fs[1] + s_fs[2] + s_fs[3];
        int npos = s_np[0] + s_np[1] + s_np[2] + s_np[3];
        double den = (npos > 0) ? (double)npos : 1.0;
        g_ploss[bid] = (double)O / (double)HW + (5.0 * (double)Bx + (double)F) / den;
    }
}

// ================= k3: final reduce =================
__global__ __launch_bounds__(256) void k3(float* out) {
    int tid = threadIdx.x;
    double a = 0.0;
    for (int i = tid; i < NOBJ; i += 256) a += (double)g_pobj[i];
    for (int i = tid; i < NB2; i += 256) a += g_ploss[i];
    for (int o = 16; o; o >>= 1) a += __shfl_down_sync(0xffffffffu, a, o);
    __shared__ double sh[8];
    if ((tid & 31) == 0) sh[tid >> 5] = a;
    __syncthreads();
    if (tid == 0) {
        double t = 0.0;
        for (int w = 0; w < 8; ++w) t += sh[w];
        out[0] = (float)(t / 64.0);
    }
}

extern "C" void kernel_launch(void* const* d_in, const int* in_sizes, int n_in,
                              void* d_out, int out_size) {
    const float* p0 = (const float*)d_in[0];
    const float* p1 = (const float*)d_in[1];
    const float* p2 = (const float*)d_in[2];
    const float* tg = (const float*)d_in[3];
    k1<<<NASSIGN + NOBJ, 128>>>(p0, p1, p2, tg);
    k2<<<NB2, 128>>>(p0, p1, p2, tg);
    k3<<<1, 256>>>((float*)d_out);
}

// round 4
// speedup vs baseline: 11.2779x; 1.0420x over previous
#include <cuda_runtime.h>
#include <math.h>

#define BATCH 64
#define NGT 40
#define CELLS_PER_B 33600
#define TOTC (BATCH*CELLS_PER_B)
#define CAP 384
#define FEPS 1e-7f
#define NASSIGN (BATCH*3*10)      // 1920 assign blocks (4 warps -> 40 GTs)
#define NOBJ (BATCH*21)           // 1344 obj blocks, 1600 cells each
#define NB2 (BATCH*3)             // 192 merge/loss blocks
#define NUNIT (BATCH*3*NGT)
#define EMAX (NGT*10)

// ---- static device scratch ----
__device__ int    A_nsel[NUNIT];
__device__ float  A_biou[NUNIT];
__device__ int    A_cell[NUNIT*10];
__device__ float  g_pobj[NOBJ];
__device__ double g_ploss[NB2];
__device__ int    g_cnt;

// focal obj term at z=0 (fast intrinsics; must match correction in k2)
__device__ __forceinline__ float obj0(float x) {
    float e = __expf(-fabsf(x));
    float sp = fmaxf(x, 0.f) + __logf(1.f + e);
    float prob = (x >= 0.f) ? __fdividef(1.f, 1.f + e) : __fdividef(e, 1.f + e);
    return 0.75f * prob * prob * sp;
}

__device__ __forceinline__ int nearest_idx(float t, int n) {
    float f = floorf(t);
    int i = (int)f;
    if (i < 0) return 0;
    if (i >= n - 1) return n - 1;
    float d1 = t - f, d2 = (f + 1.f) - t;
    return (d2 < d1) ? i + 1 : i;
}

// pred box + iou vs gt for one cell (fast intrinsics)
__device__ __forceinline__ float cell_iou(const float* __restrict__ pb, int HW, int cell,
                                          float gx, float gy, float s,
                                          float tx1, float ty1, float tx2, float ty2, float ga) {
    float v1 = pb[HW + cell], v2 = pb[2 * HW + cell];
    float v3 = pb[3 * HW + cell], v4 = pb[4 * HW + cell];
    float pcx = (__fdividef(1.f, 1.f + __expf(-v1)) + gx) * s;
    float pcy = (__fdividef(1.f, 1.f + __expf(-v2)) + gy) * s;
    float pw = __expf(fminf(fmaxf(v3, -5.f), 5.f)) * s;
    float ph = __expf(fminf(fmaxf(v4, -5.f), 5.f)) * s;
    float px1 = pcx - pw * 0.5f, py1 = pcy - ph * 0.5f;
    float px2 = pcx + pw * 0.5f, py2 = pcy + ph * 0.5f;
    float iw = fmaxf(fminf(px2, tx2) - fmaxf(px1, tx1), 0.f);
    float ih = fmaxf(fminf(py2, ty2) - fmaxf(py1, ty1), 0.f);
    float inter = iw * ih;
    float aa = (px2 - px1) * (py2 - py1);
    return __fdividef(inter, aa + ga - inter + FEPS);
}

// ================= k1: per-GT assignment (warp/GT) + dense obj partials ==============
__global__ __launch_bounds__(128) void k1(const float* __restrict__ p0,
                                          const float* __restrict__ p1,
                                          const float* __restrict__ p2,
                                          const float* __restrict__ tg) {
    int tid = threadIdx.x;
    if (blockIdx.x == 0 && tid == 0) g_cnt = 0;

    if (blockIdx.x >= NASSIGN) {
        // ---- obj role: z=0 focal loss over one contiguous 1600-cell chunk ----
        __shared__ float sh[4];
        int obid = blockIdx.x - NASSIGN;
        int b = obid / 21, c21 = obid % 21;
        const float* pr; int hw, base; float invhw;
        if (c21 < 16)      { pr = p0; hw = 25600; base = c21 * 1600;        invhw = 1.f / 25600.f; }
        else if (c21 < 20) { pr = p1; hw = 6400;  base = (c21 - 16) * 1600; invhw = 1.f / 6400.f; }
        else               { pr = p2; hw = 1600;  base = 0;                 invhw = 1.f / 1600.f; }
        const float* pb = pr + (size_t)b * 7 * hw + base;
        float acc = 0.f;
        #pragma unroll 4
        for (int j = tid; j < 1600; j += 128) acc += obj0(pb[j]);
        acc *= invhw;
        for (int o = 16; o; o >>= 1) acc += __shfl_down_sync(0xffffffffu, acc, o);
        if ((tid & 31) == 0) sh[tid >> 5] = acc;
        __syncthreads();
        if (tid == 0) g_pobj[obid] = sh[0] + sh[1] + sh[2] + sh[3];
        return;
    }

    // ---- assign role: one warp per GT ----
    __shared__ int   s_idx[4][CAP];
    __shared__ float s_cst[4][CAP];
    __shared__ int   s_sel[4][10];

    int bid = blockIdx.x;
    int b = bid / 30, rr = bid % 30;
    int lev = rr / 10, chunk = rr % 10;
    int wid = tid >> 5, lane = tid & 31;
    int g = chunk * 4 + wid;
    int u = (b * 3 + lev) * NGT + g;

    const float* tb = tg + (b * NGT + g) * 7;
    float cls = tb[0], cx = tb[1], cy = tb[2], w = tb[3], h = tb[4];
    float size = fmaxf(w, h) * 1280.f;
    bool valid = (cls == 0.f);
    int HW, W; float s; const float* pr;
    if (lev == 0)      { HW = 25600; W = 160; s = 0.00625f; pr = p0; valid = valid && (size < 128.f); }
    else if (lev == 1) { HW = 6400;  W = 80;  s = 0.0125f;  pr = p1; valid = valid && (size >= 48.f && size < 288.f); }
    else               { HW = 1600;  W = 40;  s = 0.025f;   pr = p2; valid = valid && (size >= 128.f); }
    if (!valid) { if (lane == 0) A_nsel[u] = 0; return; }
    const float* pb = pr + (size_t)b * 7 * HW;

    float inv_s = 1.f / s;
    float cxg = cx * inv_s, cyg = cy * inv_s;
    float tx1 = cx - w * 0.5f, ty1 = cy - h * 0.5f;
    float tx2 = cx + w * 0.5f, ty2 = cy + h * 0.5f;
    float bxlo = tx1 * inv_s, bxhi = tx2 * inv_s, bylo = ty1 * inv_s, byhi = ty2 * inv_s;
    float ga = (tx2 - tx1) * (ty2 - ty1);

    int x0 = (int)floorf(fminf(cxg - 2.5f, bxlo)); if (x0 < 0) x0 = 0;
    int x1 = (int)ceilf (fmaxf(cxg + 2.5f, bxhi)); if (x1 > W - 1) x1 = W - 1;
    int y0 = (int)floorf(fminf(cyg - 2.5f, bylo)); if (y0 < 0) y0 = 0;
    int y1 = (int)ceilf (fmaxf(cyg + 2.5f, byhi)); if (y1 > W - 1) y1 = W - 1;
    int rw = x1 - x0 + 1, rh = y1 - y0 + 1;
    int rn = (rw > 0 && rh > 0) ? rw * rh : 0;

    float lsum = 0.f;
    int cnt = 0;
    for (int base = 0; base < rn; base += 32) {
        int i = base + lane;
        int gxi = 0, gyi = 0; float iou = 0.f, cc = 0.f; bool cand = false;
        if (i < rn) {
            gxi = x0 + i % rw; gyi = y0 + i / rw;
            float gx = (float)gxi, gy = (float)gyi;
            bool inc = (fabsf(gx - cxg) < 2.5f) && (fabsf(gy - cyg) < 2.5f);
            bool inb = (gx >= bxlo) && (gx < bxhi) && (gy >= bylo) && (gy < byhi);
            cand = inc || inb;
            if (cand) {
                int cell = gyi * W + gxi;
                iou = cell_iou(pb, HW, cell, gx, gy, s, tx1, ty1, tx2, ty2, ga);
                float t = -pb[cell];
                cc = fmaxf(t, 0.f) + __logf(1.f + __expf(-fabsf(t))) - 3.f * __logf(iou + FEPS);
            }
        }
        unsigned mvote = __ballot_sync(0xffffffffu, cand);
        if (cand) {
            int li = cnt + __popc(mvote & ((1u << lane) - 1u));
            if (li < CAP) { s_idx[wid][li] = gyi * W + gxi; s_cst[wid][li] = cc; }
            lsum += iou;
        }
        cnt += __popc(mvote);
    }
    for (int o = 16; o; o >>= 1) lsum += __shfl_xor_sync(0xffffffffu, lsum, o);
    int ncand = cnt;
    __syncwarp();

    if (ncand == 0) {
        if (lane == 0) {
            int nx = nearest_idx(cxg, W), ny = nearest_idx(cyg, W);
            int cell = ny * W + nx;
            A_nsel[u] = 1;
            A_biou[u] = cell_iou(pb, HW, cell, (float)nx, (float)ny, s, tx1, ty1, tx2, ty2, ga);
            A_cell[u * 10] = cell;
        }
        return;
    }

    int np = (int)floorf(lsum);
    int mx = ncand < 10 ? ncand : 10;
    if (np < 1) np = 1;
    if (np > mx) np = mx;
    int m = ncand < CAP ? ncand : CAP;

    for (int k = 0; k < np; ++k) {
        float mc = 3.4e38f; int mi = 0x7fffffff;
        for (int e = lane; e < m; e += 32) {
            int ci = s_idx[wid][e];
            bool used = false;
            for (int q = 0; q < k; ++q) if (s_sel[wid][q] == ci) { used = true; break; }
            if (used) continue;
            float cc = s_cst[wid][e];
            if (cc < mc || (cc == mc && ci < mi)) { mc = cc; mi = ci; }
        }
        for (int o = 16; o; o >>= 1) {
            float oc = __shfl_xor_sync(0xffffffffu, mc, o);
            int   oi = __shfl_xor_sync(0xffffffffu, mi, o);
            if (oc < mc || (oc == mc && oi < mi)) { mc = oc; mi = oi; }
        }
        if (lane == 0) s_sel[wid][k] = mi;
        __syncwarp();
    }
    if (lane == 0) {
        A_nsel[u] = np;
        int c0 = s_sel[wid][0];
        A_biou[u] = cell_iou(pb, HW, c0, (float)(c0 % W), (float)(c0 / W), s, tx1, ty1, tx2, ty2, ga);
        for (int k = 0; k < np; ++k) A_cell[u * 10 + k] = s_sel[wid][k];
    }
}

// ================= k2: per-(b,lev) merge + sparse loss + fused final reduce ==============
__global__ __launch_bounds__(128) void k2(const float* __restrict__ p0,
                                          const float* __restrict__ p1,
                                          const float* __restrict__ p2,
                                          const float* __restrict__ tg,
                                          float* __restrict__ out) {
    __shared__ float s_tg[NGT * 7];
    __shared__ int   s_off[NGT + 1];
    __shared__ int   e_cell[EMAX];
    __shared__ int   e_g[EMAX];
    __shared__ float e_iou[EMAX];
    __shared__ float s_od[4], s_bs[4], s_fs[4];
    __shared__ int   s_np[4];
    __shared__ int   s_last;

    int bid = blockIdx.x;
    int b = bid / 3, lev = bid % 3;
    int tid = threadIdx.x;
    int HW, W; float s; const float* pr;
    if (lev == 0)      { HW = 25600; W = 160; s = 0.00625f; pr = p0; }
    else if (lev == 1) { HW = 6400;  W = 80;  s = 0.0125f;  pr = p1; }
    else               { HW = 1600;  W = 40;  s = 0.025f;   pr = p2; }
    const float* pb = pr + (size_t)b * 7 * HW;

    for (int i = tid; i < NGT * 7; i += 128) s_tg[i] = tg[b * NGT * 7 + i];
    if (tid == 0) {
        int o = 0;
        for (int g = 0; g < NGT; ++g) { s_off[g] = o; o += A_nsel[bid * NGT + g]; }
        s_off[NGT] = o;
    }
    __syncthreads();
    int tcnt = s_off[NGT];

    for (int t = tid; t < NGT * 10; t += 128) {
        int g = t / 10, k = t % 10;
        int ns = s_off[g + 1] - s_off[g];
        if (k < ns) {
            int u = bid * NGT + g;
            int e = s_off[g] + k;
            e_cell[e] = A_cell[u * 10 + k];
            e_g[e] = g;
            e_iou[e] = A_biou[u];
        }
    }
    __syncthreads();

    float od = 0.f, bs = 0.f, fs = 0.f;
    int np = 0;
    for (int e = tid; e < tcnt; e += 128) {
        int c = e_cell[e], ge = e_g[e];
        float z = e_iou[e];
        bool win = true;
        for (int e2 = 0; e2 < tcnt; ++e2) {
            if (e2 == e) continue;
            if (e_cell[e2] == c) {
                z = fmaxf(z, e_iou[e2]);
                if (e_g[e2] > ge) win = false;
            }
        }
        if (!win) continue;
        np++;

        // obj correction: focal(x,z) - focal(x,0) (formula identical to obj0)
        float x = pb[c];
        float eab = __expf(-fabsf(x));
        float l1p = __logf(1.f + eab);
        float prob = (x >= 0.f) ? __fdividef(1.f, 1.f + eab) : __fdividef(eab, 1.f + eab);
        float ce0 = fmaxf(x, 0.f) + l1p;
        float t0 = 0.75f * prob * prob * ce0;
        float ce = ce0 - x * z;
        float pt = prob * z + (1.f - prob) * (1.f - z);
        float at = 0.25f * z + 0.75f * (1.f - z);
        float om = 1.f - pt;
        od += at * om * om * ce - t0;

        float cx = s_tg[ge * 7 + 1], cy = s_tg[ge * 7 + 2];
        float w = s_tg[ge * 7 + 3], h = s_tg[ge * 7 + 4];
        float fx = s_tg[ge * 7 + 5], fy = s_tg[ge * 7 + 6];
        float cxg = cx / s, cyg = cy / s;
        int gxi = c % W, gyi = c / W;
        float gx = (float)gxi, gy = (float)gyi;
        float tb0 = cxg - gx, tb1 = cyg - gy;
        float lw = logf(w / s + FEPS), lh = logf(h / s + FEPS);

        float v1 = pb[HW + c], v2 = pb[2 * HW + c], v3 = pb[3 * HW + c], v4 = pb[4 * HW + c];
        float pcx = (1.f / (1.f + expf(-v1)) + gx) * s;
        float pcy = (1.f / (1.f + expf(-v2)) + gy) * s;
        float pw = expf(fminf(fmaxf(v3, -5.f), 5.f)) * s;
        float ph = expf(fminf(fmaxf(v4, -5.f), 5.f)) * s;
        float tcx = (tb0 + gx) * s, tcy = (tb1 + gy) * s;
        float tw = expf(lw) * s, th = expf(lh) * s;
        float px1 = pcx - pw * 0.5f, py1 = pcy - ph * 0.5f;
        float px2 = pcx + pw * 0.5f, py2 = pcy + ph * 0.5f;
        float qx1 = tcx - tw * 0.5f, qy1 = tcy - th * 0.5f;
        float qx2 = tcx + tw * 0.5f, qy2 = tcy + th * 0.5f;
        float iw = fmaxf(fminf(px2, qx2) - fmaxf(px1, qx1), 0.f);
        float ih = fmaxf(fminf(py2, qy2) - fmaxf(py1, qy1), 0.f);
        float inter = iw * ih;
        float uni = pw * ph + tw * th - inter + FEPS;
        float iou = inter / uni;
        float rho2 = (pcx - tcx) * (pcx - tcx) + (pcy - tcy) * (pcy - tcy);
        float cw2 = fmaxf(px2, qx2) - fminf(px1, qx1);
        float ch2 = fmaxf(py2, qy2) - fminf(py1, qy1);
        float c2 = cw2 * cw2 + ch2 * ch2 + FEPS;
        float dv = atanf(tw / (th + FEPS)) - atanf(pw / (ph + FEPS));
        float v = 0.405284734569351f * dv * dv;   // 4/pi^2
        float alpha = v / (1.f - iou + v + FEPS);
        float ciou = iou - rho2 / c2 - alpha * v;
        bs += 1.f - ciou;

        float pf0 = 1.f / (1.f + expf(-pb[5 * HW + c]));
        float pf1 = 1.f / (1.f + expf(-pb[6 * HW + c]));
        float d0 = fabsf(pf0 - fx);
        float d1 = fabsf(pf1 - fy);
        fs += ((d0 < 1.f) ? 0.5f * d0 * d0 : d0 - 0.5f)
            + ((d1 < 1.f) ? 0.5f * d1 * d1 : d1 - 0.5f);
    }
    for (int o = 16; o; o >>= 1) {
        od += __shfl_down_sync(0xffffffffu, od, o);
        bs += __shfl_down_sync(0xffffffffu, bs, o);
        fs += __shfl_down_sync(0xffffffffu, fs, o);
        np += __shfl_down_sync(0xffffffffu, np, o);
    }
    if ((tid & 31) == 0) { int w2 = tid >> 5; s_od[w2] = od; s_bs[w2] = bs; s_fs[w2] = fs; s_np[w2] = np; }
    __syncthreads();
    if (tid == 0) {
        float O = s_od[0] + s_od[1] + s_od[2] + s_od[3];
        float Bx = s_bs[0] + s_bs[1] + s_bs[2] + s_bs[3];
        float F = s_fs[0] + s_fs[1] + s_fs[2] + s_fs[3];
        int npos = s_np[0] + s_np[1] + s_np[2] + s_np[3];
        double den = (npos > 0) ? (double)npos : 1.0;
        g_ploss[bid] = (double)O / (double)HW + (5.0 * (double)Bx + (double)F) / den;
        __threadfence();
        s_last = (atomicAdd(&g_cnt, 1) == NB2 - 1);
    }
    __syncthreads();
    if (s_last) {
        // last block: final reduction over all partials
        double a = 0.0;
        for (int i = tid; i < NOBJ; i += 128) a += (double)__ldcg(&g_pobj[i]);
        for (int i = tid; i < NB2; i += 128) a += __ldcg(&g_ploss[i]);
        for (int o = 16; o; o >>= 1) a += __shfl_down_sync(0xffffffffu, a, o);
        __shared__ double shd[4];
        if ((tid & 31) == 0) shd[tid >> 5] = a;
        __syncthreads();
        if (tid == 0) out[0] = (float)((shd[0] + shd[1] + shd[2] + shd[3]) / 64.0);
    }
}

extern "C" void kernel_launch(void* const* d_in, const int* in_sizes, int n_in,
                              void* d_out, int out_size) {
    const float* p0 = (const float*)d_in[0];
    const float* p1 = (const float*)d_in[1];
    const float* p2 = (const float*)d_in[2];
    const float* tg = (const float*)d_in[3];
    k1<<<NASSIGN + NOBJ, 128>>>(p0, p1, p2, tg);
    k2<<<NB2, 128>>>(p0, p1, p2, tg, (float*)d_out);
}

// round 5
// speedup vs baseline: 12.0984x; 1.0727x over previous
#include <cuda_runtime.h>
#include <math.h>

#define BATCH 64
#define NGT 40
#define CAP 384
#define FEPS 1e-7f
#define NASSIGN (BATCH*3*10)      // 1920 assign blocks (4 warps -> 40 GTs each)
#define NOBJ (BATCH*21)           // 1344 obj blocks, 1600 cells each
#define NB2 (BATCH*3)             // 192 (b,lev) merge units
#define NUNIT (BATCH*3*NGT)
#define EMAX (NGT*10)
#define NDONE (NOBJ + NB2)        // 1536 completion events before final reduce

// ---- static device scratch (zero-initialized at load; counters self-reset) ----
__device__ int    A_nsel[NUNIT];
__device__ float  A_biou[NUNIT];
__device__ int    A_cell[NUNIT*10];
__device__ float  g_pobj[NOBJ];
__device__ double g_ploss[NB2];
__device__ int    g_pc[NB2];
__device__ int    g_done;

// focal obj term at z=0 (fast intrinsics; must match correction in merge)
__device__ __forceinline__ float obj0(float x) {
    float e = __expf(-fabsf(x));
    float sp = fmaxf(x, 0.f) + __logf(1.f + e);
    float prob = (x >= 0.f) ? __fdividef(1.f, 1.f + e) : __fdividef(e, 1.f + e);
    return 0.75f * prob * prob * sp;
}

__device__ __forceinline__ int nearest_idx(float t, int n) {
    float f = floorf(t);
    int i = (int)f;
    if (i < 0) return 0;
    if (i >= n - 1) return n - 1;
    float d1 = t - f, d2 = (f + 1.f) - t;
    return (d2 < d1) ? i + 1 : i;
}

// pred box + iou vs gt for one cell (fast intrinsics)
__device__ __forceinline__ float cell_iou(const float* __restrict__ pb, int HW, int cell,
                                          float gx, float gy, float s,
                                          float tx1, float ty1, float tx2, float ty2, float ga) {
    float v1 = pb[HW + cell], v2 = pb[2 * HW + cell];
    float v3 = pb[3 * HW + cell], v4 = pb[4 * HW + cell];
    float pcx = (__fdividef(1.f, 1.f + __expf(-v1)) + gx) * s;
    float pcy = (__fdividef(1.f, 1.f + __expf(-v2)) + gy) * s;
    float pw = __expf(fminf(fmaxf(v3, -5.f), 5.f)) * s;
    float ph = __expf(fminf(fmaxf(v4, -5.f), 5.f)) * s;
    float px1 = pcx - pw * 0.5f, py1 = pcy - ph * 0.5f;
    float px2 = pcx + pw * 0.5f, py2 = pcy + ph * 0.5f;
    float iw = fmaxf(fminf(px2, tx2) - fmaxf(px1, tx1), 0.f);
    float ih = fmaxf(fminf(py2, ty2) - fmaxf(py1, ty1), 0.f);
    float inter = iw * ih;
    float aa = (px2 - px1) * (py2 - py1);
    return __fdividef(inter, aa + ga - inter + FEPS);
}

__global__ __launch_bounds__(128) void k_all(const float* __restrict__ p0,
                                             const float* __restrict__ p1,
                                             const float* __restrict__ p2,
                                             const float* __restrict__ tg,
                                             float* __restrict__ out) {
    // assign-phase smem
    __shared__ int   s_idx[4][CAP];
    __shared__ float s_cst[4][CAP];
    __shared__ int   s_sel[4][10];
    // merge-phase smem
    __shared__ float s_tg[NGT * 7];
    __shared__ int   s_off[NGT + 1];
    __shared__ int   e_cell[EMAX];
    __shared__ int   e_g[EMAX];
    __shared__ float e_iou[EMAX];
    // reductions / flags
    __shared__ float s_od[4], s_bs[4], s_fs[4];
    __shared__ int   s_np[4];
    __shared__ double shd[4];
    __shared__ int   s_flag;

    int tid = threadIdx.x;

    if (blockIdx.x >= NASSIGN) {
        // ============ obj role: z=0 focal loss over one contiguous 1600-cell chunk ============
        int obid = blockIdx.x - NASSIGN;
        int b = obid / 21, c21 = obid % 21;
        const float* pr; int hw, base; float invhw;
        if (c21 < 16)      { pr = p0; hw = 25600; base = c21 * 1600;        invhw = 1.f / 25600.f; }
        else if (c21 < 20) { pr = p1; hw = 6400;  base = (c21 - 16) * 1600; invhw = 1.f / 6400.f; }
        else               { pr = p2; hw = 1600;  base = 0;                 invhw = 1.f / 1600.f; }
        const float* pb = pr + (size_t)b * 7 * hw + base;
        float acc = 0.f;
        #pragma unroll 4
        for (int j = tid; j < 1600; j += 128) acc += obj0(pb[j]);
        acc *= invhw;
        for (int o = 16; o; o >>= 1) acc += __shfl_down_sync(0xffffffffu, acc, o);
        if ((tid & 31) == 0) s_od[tid >> 5] = acc;
        __syncthreads();
        if (tid == 0) {
            g_pobj[obid] = s_od[0] + s_od[1] + s_od[2] + s_od[3];
            __threadfence();
            s_flag = (atomicAdd(&g_done, 1) == NDONE - 1);
        }
        __syncthreads();
        if (!s_flag) return;
        goto final_reduce;
    }

    {
        // ============ assign role: one warp per GT ============
        int bid = blockIdx.x;
        int b = bid / 30, rr = bid % 30;
        int lev = rr / 10, chunk = rr % 10;
        int wid = tid >> 5, lane = tid & 31;
        int g = chunk * 4 + wid;
        int mb = b * 3 + lev;                 // merge unit id
        int u = mb * NGT + g;

        const float* tb = tg + (b * NGT + g) * 7;
        float cls = tb[0], cx = tb[1], cy = tb[2], w = tb[3], h = tb[4];
        float size = fmaxf(w, h) * 1280.f;
        bool valid = (cls == 0.f);
        int HW, W; float s; const float* pr;
        if (lev == 0)      { HW = 25600; W = 160; s = 0.00625f; pr = p0; valid = valid && (size < 128.f); }
        else if (lev == 1) { HW = 6400;  W = 80;  s = 0.0125f;  pr = p1; valid = valid && (size >= 48.f && size < 288.f); }
        else               { HW = 1600;  W = 40;  s = 0.025f;   pr = p2; valid = valid && (size >= 128.f); }

        if (!valid) {
            if (lane == 0) A_nsel[u] = 0;
        } else {
            const float* pb = pr + (size_t)b * 7 * HW;
            float inv_s = 1.f / s;
            float cxg = cx * inv_s, cyg = cy * inv_s;
            float tx1 = cx - w * 0.5f, ty1 = cy - h * 0.5f;
            float tx2 = cx + w * 0.5f, ty2 = cy + h * 0.5f;
            float bxlo = tx1 * inv_s, bxhi = tx2 * inv_s, bylo = ty1 * inv_s, byhi = ty2 * inv_s;
            float ga = (tx2 - tx1) * (ty2 - ty1);

            int x0 = (int)floorf(fminf(cxg - 2.5f, bxlo)); if (x0 < 0) x0 = 0;
            int x1 = (int)ceilf (fmaxf(cxg + 2.5f, bxhi)); if (x1 > W - 1) x1 = W - 1;
            int y0 = (int)floorf(fminf(cyg - 2.5f, bylo)); if (y0 < 0) y0 = 0;
            int y1 = (int)ceilf (fmaxf(cyg + 2.5f, byhi)); if (y1 > W - 1) y1 = W - 1;
            int rw = x1 - x0 + 1, rh = y1 - y0 + 1;
            int rn = (rw > 0 && rh > 0) ? rw * rh : 0;

            float lsum = 0.f;
            int cnt = 0;
            for (int base = 0; base < rn; base += 32) {
                int i = base + lane;
                int gxi = 0, gyi = 0; float iou = 0.f, cc = 0.f; bool cand = false;
                if (i < rn) {
                    gxi = x0 + i % rw; gyi = y0 + i / rw;
                    float gx = (float)gxi, gy = (float)gyi;
                    bool inc = (fabsf(gx - cxg) < 2.5f) && (fabsf(gy - cyg) < 2.5f);
                    bool inb = (gx >= bxlo) && (gx < bxhi) && (gy >= bylo) && (gy < byhi);
                    cand = inc || inb;
                    if (cand) {
                        int cell = gyi * W + gxi;
                        iou = cell_iou(pb, HW, cell, gx, gy, s, tx1, ty1, tx2, ty2, ga);
                        float t = -pb[cell];
                        cc = fmaxf(t, 0.f) + __logf(1.f + __expf(-fabsf(t))) - 3.f * __logf(iou + FEPS);
                    }
                }
                unsigned mvote = __ballot_sync(0xffffffffu, cand);
                if (cand) {
                    int li = cnt + __popc(mvote & ((1u << lane) - 1u));
                    if (li < CAP) { s_idx[wid][li] = gyi * W + gxi; s_cst[wid][li] = cc; }
                    lsum += iou;
                }
                cnt += __popc(mvote);
            }
            for (int o = 16; o; o >>= 1) lsum += __shfl_xor_sync(0xffffffffu, lsum, o);
            int ncand = cnt;
            __syncwarp();

            if (ncand == 0) {
                if (lane == 0) {
                    int nx = nearest_idx(cxg, W), ny = nearest_idx(cyg, W);
                    int cell = ny * W + nx;
                    A_nsel[u] = 1;
                    A_biou[u] = cell_iou(pb, HW, cell, (float)nx, (float)ny, s, tx1, ty1, tx2, ty2, ga);
                    A_cell[u * 10] = cell;
                }
            } else {
                int np = (int)floorf(lsum);
                int mx = ncand < 10 ? ncand : 10;
                if (np < 1) np = 1;
                if (np > mx) np = mx;
                int m = ncand < CAP ? ncand : CAP;

                for (int k = 0; k < np; ++k) {
                    float mc = 3.4e38f; int mi = 0x7fffffff;
                    for (int e = lane; e < m; e += 32) {
                        int ci = s_idx[wid][e];
                        bool used = false;
                        for (int q = 0; q < k; ++q) if (s_sel[wid][q] == ci) { used = true; break; }
                        if (used) continue;
                        float cc = s_cst[wid][e];
                        if (cc < mc || (cc == mc && ci < mi)) { mc = cc; mi = ci; }
                    }
                    for (int o = 16; o; o >>= 1) {
                        float oc = __shfl_xor_sync(0xffffffffu, mc, o);
                        int   oi = __shfl_xor_sync(0xffffffffu, mi, o);
                        if (oc < mc || (oc == mc && oi < mi)) { mc = oc; mi = oi; }
                    }
                    if (lane == 0) s_sel[wid][k] = mi;
                    __syncwarp();
                }
                if (lane == 0) {
                    A_nsel[u] = np;
                    int c0 = s_sel[wid][0];
                    A_biou[u] = cell_iou(pb, HW, c0, (float)(c0 % W), (float)(c0 / W), s, tx1, ty1, tx2, ty2, ga);
                    for (int k = 0; k < np; ++k) A_cell[u * 10 + k] = s_sel[wid][k];
                }
            }
        }
        __threadfence();       // make this thread's global writes visible pre-counter
        __syncthreads();
        if (tid == 0) s_flag = (atomicAdd(&g_pc[mb], 1) == 9);
        __syncthreads();
        if (!s_flag) return;

        // ============ merge role: last-arriving block of this (b,lev) ============
        __threadfence();       // acquire side: order counter read before scratch reads
        {
            const float* pbm = pr + (size_t)b * 7 * HW;   // level params already in scope
            for (int i = tid; i < NGT * 7; i += 128) s_tg[i] = tg[b * NGT * 7 + i];
            if (tid == 0) {
                int o = 0;
                for (int gg = 0; gg < NGT; ++gg) { s_off[gg] = o; o += __ldcg(&A_nsel[mb * NGT + gg]); }
                s_off[NGT] = o;
            }
            __syncthreads();
            int tcnt = s_off[NGT];

            for (int t = tid; t < NGT * 10; t += 128) {
                int gg = t / 10, k = t % 10;
                int ns = s_off[gg + 1] - s_off[gg];
                if (k < ns) {
                    int uu = mb * NGT + gg;
                    int e = s_off[gg] + k;
                    e_cell[e] = __ldcg(&A_cell[uu * 10 + k]);
                    e_g[e] = gg;
                    e_iou[e] = __ldcg(&A_biou[uu]);
                }
            }
            __syncthreads();

            float od = 0.f, bs = 0.f, fs = 0.f;
            int np = 0;
            for (int e = tid; e < tcnt; e += 128) {
                int c = e_cell[e], ge = e_g[e];
                float z = e_iou[e];
                bool win = true;
                for (int e2 = 0; e2 < tcnt; ++e2) {
                    if (e2 == e) continue;
                    if (e_cell[e2] == c) {
                        z = fmaxf(z, e_iou[e2]);
                        if (e_g[e2] > ge) win = false;
                    }
                }
                if (!win) continue;
                np++;

                // obj correction: focal(x,z) - focal(x,0) (formula identical to obj0)
                float x = pbm[c];
                float eab = __expf(-fabsf(x));
                float l1p = __logf(1.f + eab);
                float prob = (x >= 0.f) ? __fdividef(1.f, 1.f + eab) : __fdividef(eab, 1.f + eab);
                float ce0 = fmaxf(x, 0.f) + l1p;
                float t0 = 0.75f * prob * prob * ce0;
                float ce = ce0 - x * z;
                float pt = prob * z + (1.f - prob) * (1.f - z);
                float at = 0.25f * z + 0.75f * (1.f - z);
                float om = 1.f - pt;
                od += at * om * om * ce - t0;

                float cxm = s_tg[ge * 7 + 1], cym = s_tg[ge * 7 + 2];
                float wm = s_tg[ge * 7 + 3], hm = s_tg[ge * 7 + 4];
                float fx = s_tg[ge * 7 + 5], fy = s_tg[ge * 7 + 6];
                float cxg2 = cxm / s, cyg2 = cym / s;
                int gxi = c % W, gyi = c / W;
                float gx = (float)gxi, gy = (float)gyi;
                float tb0 = cxg2 - gx, tb1 = cyg2 - gy;
                float lw = logf(wm / s + FEPS), lh = logf(hm / s + FEPS);

                float v1 = pbm[HW + c], v2 = pbm[2 * HW + c], v3 = pbm[3 * HW + c], v4 = pbm[4 * HW + c];
                float pcx = (1.f / (1.f + expf(-v1)) + gx) * s;
                float pcy = (1.f / (1.f + expf(-v2)) + gy) * s;
                float pw = expf(fminf(fmaxf(v3, -5.f), 5.f)) * s;
                float ph = expf(fminf(fmaxf(v4, -5.f), 5.f)) * s;
                float tcx = (tb0 + gx) * s, tcy = (tb1 + gy) * s;
                float tw = expf(lw) * s, th = expf(lh) * s;
                float px1 = pcx - pw * 0.5f, py1 = pcy - ph * 0.5f;
                float px2 = pcx + pw * 0.5f, py2 = pcy + ph * 0.5f;
                float qx1 = tcx - tw * 0.5f, qy1 = tcy - th * 0.5f;
                float qx2 = tcx + tw * 0.5f, qy2 = tcy + th * 0.5f;
                float iw = fmaxf(fminf(px2, qx2) - fmaxf(px1, qx1), 0.f);
                float ih = fmaxf(fminf(py2, qy2) - fmaxf(py1, qy1), 0.f);
                float inter = iw * ih;
                float uni = pw * ph + tw * th - inter + FEPS;
                float iou = inter / uni;
                float rho2 = (pcx - tcx) * (pcx - tcx) + (pcy - tcy) * (pcy - tcy);
                float cw2 = fmaxf(px2, qx2) - fminf(px1, qx1);
                float ch2 = fmaxf(py2, qy2) - fminf(py1, qy1);
                float c2 = cw2 * cw2 + ch2 * ch2 + FEPS;
                float dv = atanf(tw / (th + FEPS)) - atanf(pw / (ph + FEPS));
                float v = 0.405284734569351f * dv * dv;   // 4/pi^2
                float alpha = v / (1.f - iou + v + FEPS);
                float ciou = iou - rho2 / c2 - alpha * v;
                bs += 1.f - ciou;

                float pf0 = 1.f / (1.f + expf(-pbm[5 * HW + c]));
                float pf1 = 1.f / (1.f + expf(-pbm[6 * HW + c]));
                float d0 = fabsf(pf0 - fx);
                float d1 = fabsf(pf1 - fy);
                fs += ((d0 < 1.f) ? 0.5f * d0 * d0 : d0 - 0.5f)
                    + ((d1 < 1.f) ? 0.5f * d1 * d1 : d1 - 0.5f);
            }
            for (int o = 16; o; o >>= 1) {
                od += __shfl_down_sync(0xffffffffu, od, o);
                bs += __shfl_down_sync(0xffffffffu, bs, o);
                fs += __shfl_down_sync(0xffffffffu, fs, o);
                np += __shfl_down_sync(0xffffffffu, np, o);
            }
            if ((tid & 31) == 0) { int w2 = tid >> 5; s_od[w2] = od; s_bs[w2] = bs; s_fs[w2] = fs; s_np[w2] = np; }
            __syncthreads();
            if (tid == 0) {
                float O = s_od[0] + s_od[1] + s_od[2] + s_od[3];
                float Bx = s_bs[0] + s_bs[1] + s_bs[2] + s_bs[3];
                float F = s_fs[0] + s_fs[1] + s_fs[2] + s_fs[3];
                int npos = s_np[0] + s_np[1] + s_np[2] + s_np[3];
                double den = (npos > 0) ? (double)npos : 1.0;
                g_ploss[mb] = (double)O / (double)HW + (5.0 * (double)Bx + (double)F) / den;
                __threadfence();
                s_flag = (atomicAdd(&g_done, 1) == NDONE - 1);
            }
            __syncthreads();
            if (!s_flag) return;
        }
    }

final_reduce:
    // ============ final role: last completion event reduces everything ============
    {
        __threadfence();
        double a = 0.0;
        for (int i = tid; i < NOBJ; i += 128) a += (double)__ldcg(&g_pobj[i]);
        for (int i = tid; i < NB2; i += 128) a += __ldcg(&g_ploss[i]);
        for (int o = 16; o; o >>= 1) a += __shfl_down_sync(0xffffffffu, a, o);
        if ((tid & 31) == 0) shd[tid >> 5] = a;
        __syncthreads();
        if (tid == 0) out[0] = (float)((shd[0] + shd[1] + shd[2] + shd[3]) / 64.0);
        // reset counters for next graph replay (launches are stream-serialized)
        for (int i = tid; i < NB2; i += 128) g_pc[i] = 0;
        if (tid == 0) g_done = 0;
    }
}

extern "C" void kernel_launch(void* const* d_in, const int* in_sizes, int n_in,
                              void* d_out, int out_size) {
    const float* p0 = (const float*)d_in[0];
    const float* p1 = (const float*)d_in[1];
    const float* p2 = (const float*)d_in[2];
    const float* tg = (const float*)d_in[3];
    k_all<<<NASSIGN + NOBJ, 128>>>(p0, p1, p2, tg, (float*)d_out);
}